// round 5
// baseline (speedup 1.0000x reference)
#include <cuda_runtime.h>
#include <math.h>
#include <stdint.h>
#include <stddef.h>

// ---------------- problem constants ----------------
#define B_     4096
#define L_     32
#define FEAT_  128
#define H_     512
#define C_     256
#define FM_    64
#define G4H_   (4 * H_)       // 2048

// ---------------- scratch (device globals; no allocation allowed) ----------------
__device__ float g_gates[(size_t)B_ * G4H_];     // 33.5 MB  gate preactivations per step
__device__ float g_h[(size_t)B_ * H_];           // hidden state
__device__ float g_c[(size_t)B_ * H_];           // cell state
__device__ float g_h1[(size_t)B_ * L_ * H_];     // 268 MB   layer-0 output sequence
__device__ float g_bias0[G4H_];                  // bih0+bhh0
__device__ float g_bias1[G4H_];                  // bih1+bhh1
__device__ float g_immm[(size_t)B_ * FM_];       // masked y
__device__ float g_t1[(size_t)B_ * H_];
__device__ float g_t2[(size_t)B_ * H_];
__device__ float g_cat[(size_t)B_ * 2 * C_];
__device__ float g_fused[(size_t)B_ * 2 * C_];

// ---------------- SGEMM: C = [A1|A2] @ [B1|B2]^T (+bias, epilogues) ----------------
// A is M x K (rows from A1 for k<KA, A2 for k>=KA), B is N x K row-major (so B^T used).
// All of M, N divisible by 128; K, KA divisible by 8.
// epi: 0 = store acc+bias ; 1 = relu(acc+bias) ; 2 = aux[m,n]*sigmoid(acc+bias)
#define BM 128
#define BN 128
#define BK 8
#define TM 8
#define TN 8

__global__ __launch_bounds__(256, 2)
void sgemm_dual(const float* __restrict__ A1, int lda1,
                const float* __restrict__ A2, int lda2, int KA,
                const float* __restrict__ B1, int ldb1,
                const float* __restrict__ B2, int ldb2,
                const float* __restrict__ bias,
                const float* __restrict__ aux, int ldaux,
                float* __restrict__ C, int ldc,
                int M, int N, int K, int epi)
{
    __shared__ __align__(16) float As[2][BK][BM + 4];
    __shared__ __align__(16) float Bs[2][BK][BN + 4];

    const int tid = threadIdx.x;
    const int tx = tid & 15;          // 0..15  -> col group
    const int ty = tid >> 4;          // 0..15  -> row group
    const int rowBase = blockIdx.y * BM;
    const int colBase = blockIdx.x * BN;

    const int lr = tid >> 1;          // 0..127 loading row
    const int lk = (tid & 1) * 4;     // 0 or 4 loading k offset

    float acc[TM][TN];
#pragma unroll
    for (int i = 0; i < TM; i++)
#pragma unroll
        for (int j = 0; j < TN; j++) acc[i][j] = 0.f;

    const int ntiles = K / BK;

    // prologue: load k-tile 0
    {
        const float* Ap = (0 < KA) ? (A1 + (size_t)(rowBase + lr) * lda1 + lk)
                                   : (A2 + (size_t)(rowBase + lr) * lda2 + lk);
        const float* Bp = (0 < KA) ? (B1 + (size_t)(colBase + lr) * ldb1 + lk)
                                   : (B2 + (size_t)(colBase + lr) * ldb2 + lk);
        float4 av = *(const float4*)Ap;
        float4 bv = *(const float4*)Bp;
        As[0][lk + 0][lr] = av.x; As[0][lk + 1][lr] = av.y;
        As[0][lk + 2][lr] = av.z; As[0][lk + 3][lr] = av.w;
        Bs[0][lk + 0][lr] = bv.x; Bs[0][lk + 1][lr] = bv.y;
        Bs[0][lk + 2][lr] = bv.z; Bs[0][lk + 3][lr] = bv.w;
    }
    __syncthreads();

    for (int kt = 0; kt < ntiles; kt++) {
        const int buf = kt & 1;
        float4 av2, bv2;
        const bool hasNext = (kt + 1 < ntiles);
        if (hasNext) {
            const int k0 = (kt + 1) * BK;
            const float* Ap = (k0 < KA) ? (A1 + (size_t)(rowBase + lr) * lda1 + k0 + lk)
                                        : (A2 + (size_t)(rowBase + lr) * lda2 + (k0 - KA) + lk);
            const float* Bp = (k0 < KA) ? (B1 + (size_t)(colBase + lr) * ldb1 + k0 + lk)
                                        : (B2 + (size_t)(colBase + lr) * ldb2 + (k0 - KA) + lk);
            av2 = *(const float4*)Ap;
            bv2 = *(const float4*)Bp;
        }

#pragma unroll
        for (int kk = 0; kk < BK; kk++) {
            float4 a0 = *(const float4*)&As[buf][kk][ty * TM];
            float4 a1 = *(const float4*)&As[buf][kk][ty * TM + 4];
            float4 b0 = *(const float4*)&Bs[buf][kk][tx * TN];
            float4 b1 = *(const float4*)&Bs[buf][kk][tx * TN + 4];
            float a[TM] = {a0.x, a0.y, a0.z, a0.w, a1.x, a1.y, a1.z, a1.w};
            float b[TN] = {b0.x, b0.y, b0.z, b0.w, b1.x, b1.y, b1.z, b1.w};
#pragma unroll
            for (int i = 0; i < TM; i++)
#pragma unroll
                for (int j = 0; j < TN; j++)
                    acc[i][j] = fmaf(a[i], b[j], acc[i][j]);
        }

        if (hasNext) {
            const int nb = buf ^ 1;
            As[nb][lk + 0][lr] = av2.x; As[nb][lk + 1][lr] = av2.y;
            As[nb][lk + 2][lr] = av2.z; As[nb][lk + 3][lr] = av2.w;
            Bs[nb][lk + 0][lr] = bv2.x; Bs[nb][lk + 1][lr] = bv2.y;
            Bs[nb][lk + 2][lr] = bv2.z; Bs[nb][lk + 3][lr] = bv2.w;
            __syncthreads();
        }
    }

    // epilogue
#pragma unroll
    for (int i = 0; i < TM; i++) {
        const int r = rowBase + ty * TM + i;
        const size_t base = (size_t)r * ldc;
#pragma unroll
        for (int j = 0; j < TN; j++) {
            const int cidx = colBase + tx * TN + j;
            float v = acc[i][j];
            if (bias) v += bias[cidx];
            if (epi == 1) {
                v = v > 0.f ? v : 0.f;
            } else if (epi == 2) {
                const float s = 1.f / (1.f + expf(-v));
                v = aux[(size_t)r * ldaux + cidx] * s;
            }
            C[base + cidx] = v;
        }
    }
}

// ---------------- elementwise kernels ----------------
__device__ __forceinline__ float dsigmoid(float x) { return 1.f / (1.f + expf(-x)); }

__global__ void prep_bias_kernel(const float* __restrict__ bih0, const float* __restrict__ bhh0,
                                 const float* __restrict__ bih1, const float* __restrict__ bhh1)
{
    int i = blockIdx.x * blockDim.x + threadIdx.x;
    if (i < G4H_) {
        g_bias0[i] = bih0[i] + bhh0[i];
        g_bias1[i] = bih1[i] + bhh1[i];
    }
}

__global__ void zero_hc_kernel()
{
    int i = blockIdx.x * blockDim.x + threadIdx.x;
    if (i < B_ * H_) { g_h[i] = 0.f; g_c[i] = 0.f; }
}

// gates layout per row: [i(512) f(512) g(512) o(512)]
__global__ void lstm_cell_kernel(int t, int storeSeq)
{
    int idx = blockIdx.x * blockDim.x + threadIdx.x;
    if (idx >= B_ * H_) return;
    const int b = idx >> 9;          // /512
    const int j = idx & 511;
    const float* gr = g_gates + (size_t)b * G4H_;
    const float ig = dsigmoid(gr[j]);
    const float fg = dsigmoid(gr[H_ + j]);
    const float gg = tanhf(gr[2 * H_ + j]);
    const float og = dsigmoid(gr[3 * H_ + j]);
    const float cn = fg * g_c[idx] + ig * gg;
    const float hn = og * tanhf(cn);
    g_c[idx] = cn;
    g_h[idx] = hn;
    if (storeSeq) g_h1[(size_t)b * (L_ * H_) + (size_t)t * H_ + j] = hn;
}

// top-8 wideband beams per row + build masked mm input. One warp per row.
__global__ void topk_mask_kernel(const float* __restrict__ out_sub, const float* __restrict__ y)
{
    const int warp = (blockIdx.x * blockDim.x + threadIdx.x) >> 5;
    const int lane = threadIdx.x & 31;
    if (warp >= B_) return;
    const float* row = out_sub + (size_t)warp * C_;
    float p = 0.f;
#pragma unroll
    for (int k = 0; k < 8; k++) p += row[lane * 8 + k];

    unsigned selmask = 0;
    float v = p;
#pragma unroll
    for (int it = 0; it < 8; it++) {
        float m = v;
        int mi = lane;
#pragma unroll
        for (int off = 16; off; off >>= 1) {
            const float ov = __shfl_xor_sync(0xffffffffu, m, off);
            const int   oi = __shfl_xor_sync(0xffffffffu, mi, off);
            if (ov > m || (ov == m && oi < mi)) { m = ov; mi = oi; }
        }
        selmask |= 1u << mi;           // all lanes agree on mi
        if (lane == mi) v = -INFINITY;
    }
    const float sel = ((selmask >> lane) & 1u) ? 1.f : 0.f;
    const size_t base = (size_t)warp * FM_ + 2 * lane;
    g_immm[base]     = y[base]     * sel;
    g_immm[base + 1] = y[base + 1] * sel;
}

__global__ void cat_kernel(const float* __restrict__ out_sub, const float* __restrict__ out_mm)
{
    int idx = blockIdx.x * blockDim.x + threadIdx.x;
    if (idx >= B_ * 2 * C_) return;
    const int b = idx >> 9;
    const int j = idx & 511;
    g_cat[idx] = (j < C_) ? out_sub[(size_t)b * C_ + j] : out_mm[(size_t)b * C_ + (j - C_)];
}

// ---------------- host launcher ----------------
static inline void launch_gemm(const float* A, int lda, const float* Bw, int ldb,
                               const float* bias, const float* aux, int ldaux,
                               float* C, int ldc, int M, int N, int K, int epi)
{
    dim3 grid(N / BN, M / BM), block(256);
    sgemm_dual<<<grid, block>>>(A, lda, A, lda, K, Bw, ldb, Bw, ldb,
                                bias, aux, ldaux, C, ldc, M, N, K, epi);
}

extern "C" void kernel_launch(void* const* d_in, const int* in_sizes, int n_in,
                              void* d_out, int out_size)
{
    const float* x    = (const float*)d_in[0];
    const float* y    = (const float*)d_in[1];
    const float* Wih0 = (const float*)d_in[2];
    const float* Whh0 = (const float*)d_in[3];
    const float* bih0 = (const float*)d_in[4];
    const float* bhh0 = (const float*)d_in[5];
    const float* Wih1 = (const float*)d_in[6];
    const float* Whh1 = (const float*)d_in[7];
    const float* bih1 = (const float*)d_in[8];
    const float* bhh1 = (const float*)d_in[9];
    const float* decW = (const float*)d_in[10];
    const float* decb = (const float*)d_in[11];
    const float* mmW1 = (const float*)d_in[12];
    const float* mmb1 = (const float*)d_in[13];
    const float* mmW2 = (const float*)d_in[14];
    const float* mmb2 = (const float*)d_in[15];
    const float* mmW3 = (const float*)d_in[16];
    const float* mmb3 = (const float*)d_in[17];
    const float* attW = (const float*)d_in[18];
    const float* attb = (const float*)d_in[19];
    const float* fuW1 = (const float*)d_in[20];
    const float* fub1 = (const float*)d_in[21];
    const float* fuW2 = (const float*)d_in[22];
    const float* fub2 = (const float*)d_in[23];
    const float* fuW3 = (const float*)d_in[24];
    const float* fub3 = (const float*)d_in[25];

    float* out     = (float*)d_out;
    float* out_sub = out;
    float* out_mm  = out + (size_t)B_ * C_;
    float* out_fu  = out + (size_t)2 * B_ * C_;

    float *gates, *h, *c, *h1, *bs0, *bs1, *immm, *t1, *t2, *cat, *fused;
    cudaGetSymbolAddress((void**)&gates, g_gates);
    cudaGetSymbolAddress((void**)&h,     g_h);
    cudaGetSymbolAddress((void**)&c,     g_c);
    cudaGetSymbolAddress((void**)&h1,    g_h1);
    cudaGetSymbolAddress((void**)&bs0,   g_bias0);
    cudaGetSymbolAddress((void**)&bs1,   g_bias1);
    cudaGetSymbolAddress((void**)&immm,  g_immm);
    cudaGetSymbolAddress((void**)&t1,    g_t1);
    cudaGetSymbolAddress((void**)&t2,    g_t2);
    cudaGetSymbolAddress((void**)&cat,   g_cat);
    cudaGetSymbolAddress((void**)&fused, g_fused);
    (void)c; (void)in_sizes; (void)n_in; (void)out_size;

    const int hcBlocks = (B_ * H_ + 255) / 256;

    prep_bias_kernel<<<(G4H_ + 255) / 256, 256>>>(bih0, bhh0, bih1, bhh1);

    // ---- LSTM layer 0: gates = [x_t | h] @ [Wih0 | Whh0]^T + (bih0+bhh0) ----
    zero_hc_kernel<<<hcBlocks, 256>>>();
    {
        dim3 grid(G4H_ / BN, B_ / BM), block(256);
        for (int t = 0; t < L_; t++) {
            sgemm_dual<<<grid, block>>>(x + (size_t)t * FEAT_, L_ * FEAT_,   // A1 = x[:,t,:]
                                        h, H_, FEAT_,                        // A2 = h, split at KA=128
                                        Wih0, FEAT_, Whh0, H_,
                                        bs0, nullptr, 0,
                                        gates, G4H_, B_, G4H_, FEAT_ + H_, 0);
            lstm_cell_kernel<<<hcBlocks, 256>>>(t, 1);
        }
    }

    // ---- LSTM layer 1: gates = [h1_t | h] @ [Wih1 | Whh1]^T + (bih1+bhh1) ----
    zero_hc_kernel<<<hcBlocks, 256>>>();
    {
        dim3 grid(G4H_ / BN, B_ / BM), block(256);
        for (int t = 0; t < L_; t++) {
            sgemm_dual<<<grid, block>>>(h1 + (size_t)t * H_, L_ * H_,        // A1 = h1[:,t,:]
                                        h, H_, H_,                           // A2 = h, split at KA=512
                                        Wih1, H_, Whh1, H_,
                                        bs1, nullptr, 0,
                                        gates, G4H_, B_, G4H_, 2 * H_, 0);
            lstm_cell_kernel<<<hcBlocks, 256>>>(t, 0);
        }
    }

    // ---- decoder: out_sub = h2_last @ decW^T + decb ----
    launch_gemm(h, H_, decW, H_, decb, nullptr, 0, out_sub, C_, B_, C_, H_, 0);

    // ---- top-8 beam mask -> input_mm ----
    topk_mask_kernel<<<(B_ * 32 + 255) / 256, 256>>>(out_sub, y);

    // ---- mm MLP ----
    launch_gemm(immm, FM_, mmW1, FM_, mmb1, nullptr, 0, t1, H_, B_, H_, FM_, 1);
    launch_gemm(t1, H_, mmW2, H_, mmb2, nullptr, 0, t2, H_, B_, H_, H_, 1);
    launch_gemm(t2, H_, mmW3, H_, mmb3, nullptr, 0, out_mm, C_, B_, C_, H_, 0);

    // ---- gated fusion ----
    cat_kernel<<<(B_ * 2 * C_ + 255) / 256, 256>>>(out_sub, out_mm);
    launch_gemm(cat, 2 * C_, attW, 2 * C_, attb, cat, 2 * C_, fused, 2 * C_, B_, 2 * C_, 2 * C_, 2);
    launch_gemm(fused, 2 * C_, fuW1, 2 * C_, fub1, nullptr, 0, t1, H_, B_, H_, 2 * C_, 1);
    launch_gemm(t1, H_, fuW2, H_, fub2, nullptr, 0, t2, H_, B_, H_, H_, 1);
    launch_gemm(t2, H_, fuW3, H_, fub3, nullptr, 0, out_fu, C_, B_, C_, H_, 0);
}

// round 6
// speedup vs baseline: 1.0018x; 1.0018x over previous
#include <cuda_runtime.h>
#include <math.h>
#include <stdint.h>
#include <stddef.h>

// ---------------- problem constants ----------------
#define B_     4096
#define L_     32
#define FEAT_  128
#define H_     512
#define C_     256
#define FM_    64
#define G4H_   (4 * H_)       // 2048

// ---------------- scratch (device globals; no allocation allowed) ----------------
__device__ float g_gates[(size_t)B_ * G4H_];     // 33.5 MB  gate preactivations per step
__device__ float g_h[(size_t)B_ * H_];           // hidden state
__device__ float g_c[(size_t)B_ * H_];           // cell state
__device__ float g_h1[(size_t)B_ * L_ * H_];     // 268 MB   layer-0 output sequence
__device__ float g_bias0[G4H_];                  // bih0+bhh0
__device__ float g_bias1[G4H_];                  // bih1+bhh1
__device__ float g_immm[(size_t)B_ * FM_];       // masked y
__device__ float g_t1[(size_t)B_ * H_];
__device__ float g_t2[(size_t)B_ * H_];
__device__ float g_cat[(size_t)B_ * 2 * C_];
__device__ float g_fused[(size_t)B_ * 2 * C_];

// ---------------- SGEMM: C = [A1|A2] @ [B1|B2]^T (+bias, epilogues) ----------------
// A is M x K (rows from A1 for k<KA, A2 for k>=KA), B is N x K row-major (so B^T used).
// All of M, N divisible by 128; K, KA divisible by 8.
// epi: 0 = store acc+bias ; 1 = relu(acc+bias) ; 2 = aux[m,n]*sigmoid(acc+bias)
#define BM 128
#define BN 128
#define BK 8
#define TM 8
#define TN 8

__global__ __launch_bounds__(256, 2)
void sgemm_dual(const float* __restrict__ A1, int lda1,
                const float* __restrict__ A2, int lda2, int KA,
                const float* __restrict__ B1, int ldb1,
                const float* __restrict__ B2, int ldb2,
                const float* __restrict__ bias,
                const float* __restrict__ aux, int ldaux,
                float* __restrict__ C, int ldc,
                int M, int N, int K, int epi)
{
    __shared__ __align__(16) float As[2][BK][BM + 4];
    __shared__ __align__(16) float Bs[2][BK][BN + 4];

    const int tid = threadIdx.x;
    const int tx = tid & 15;          // 0..15  -> col group
    const int ty = tid >> 4;          // 0..15  -> row group
    const int rowBase = blockIdx.y * BM;
    const int colBase = blockIdx.x * BN;

    const int lr = tid >> 1;          // 0..127 loading row
    const int lk = (tid & 1) * 4;     // 0 or 4 loading k offset

    float acc[TM][TN];
#pragma unroll
    for (int i = 0; i < TM; i++)
#pragma unroll
        for (int j = 0; j < TN; j++) acc[i][j] = 0.f;

    const int ntiles = K / BK;

    // prologue: load k-tile 0
    {
        const float* Ap = (0 < KA) ? (A1 + (size_t)(rowBase + lr) * lda1 + lk)
                                   : (A2 + (size_t)(rowBase + lr) * lda2 + lk);
        const float* Bp = (0 < KA) ? (B1 + (size_t)(colBase + lr) * ldb1 + lk)
                                   : (B2 + (size_t)(colBase + lr) * ldb2 + lk);
        float4 av = *(const float4*)Ap;
        float4 bv = *(const float4*)Bp;
        As[0][lk + 0][lr] = av.x; As[0][lk + 1][lr] = av.y;
        As[0][lk + 2][lr] = av.z; As[0][lk + 3][lr] = av.w;
        Bs[0][lk + 0][lr] = bv.x; Bs[0][lk + 1][lr] = bv.y;
        Bs[0][lk + 2][lr] = bv.z; Bs[0][lk + 3][lr] = bv.w;
    }
    __syncthreads();

    for (int kt = 0; kt < ntiles; kt++) {
        const int buf = kt & 1;
        float4 av2, bv2;
        const bool hasNext = (kt + 1 < ntiles);
        if (hasNext) {
            const int k0 = (kt + 1) * BK;
            const float* Ap = (k0 < KA) ? (A1 + (size_t)(rowBase + lr) * lda1 + k0 + lk)
                                        : (A2 + (size_t)(rowBase + lr) * lda2 + (k0 - KA) + lk);
            const float* Bp = (k0 < KA) ? (B1 + (size_t)(colBase + lr) * ldb1 + k0 + lk)
                                        : (B2 + (size_t)(colBase + lr) * ldb2 + (k0 - KA) + lk);
            av2 = *(const float4*)Ap;
            bv2 = *(const float4*)Bp;
        }

#pragma unroll
        for (int kk = 0; kk < BK; kk++) {
            float4 a0 = *(const float4*)&As[buf][kk][ty * TM];
            float4 a1 = *(const float4*)&As[buf][kk][ty * TM + 4];
            float4 b0 = *(const float4*)&Bs[buf][kk][tx * TN];
            float4 b1 = *(const float4*)&Bs[buf][kk][tx * TN + 4];
            float a[TM] = {a0.x, a0.y, a0.z, a0.w, a1.x, a1.y, a1.z, a1.w};
            float b[TN] = {b0.x, b0.y, b0.z, b0.w, b1.x, b1.y, b1.z, b1.w};
#pragma unroll
            for (int i = 0; i < TM; i++)
#pragma unroll
                for (int j = 0; j < TN; j++)
                    acc[i][j] = fmaf(a[i], b[j], acc[i][j]);
        }

        if (hasNext) {
            const int nb = buf ^ 1;
            As[nb][lk + 0][lr] = av2.x; As[nb][lk + 1][lr] = av2.y;
            As[nb][lk + 2][lr] = av2.z; As[nb][lk + 3][lr] = av2.w;
            Bs[nb][lk + 0][lr] = bv2.x; Bs[nb][lk + 1][lr] = bv2.y;
            Bs[nb][lk + 2][lr] = bv2.z; Bs[nb][lk + 3][lr] = bv2.w;
            __syncthreads();
        }
    }

    // epilogue
#pragma unroll
    for (int i = 0; i < TM; i++) {
        const int r = rowBase + ty * TM + i;
        const size_t base = (size_t)r * ldc;
#pragma unroll
        for (int j = 0; j < TN; j++) {
            const int cidx = colBase + tx * TN + j;
            float v = acc[i][j];
            if (bias) v += bias[cidx];
            if (epi == 1) {
                v = v > 0.f ? v : 0.f;
            } else if (epi == 2) {
                const float s = 1.f / (1.f + expf(-v));
                v = aux[(size_t)r * ldaux + cidx] * s;
            }
            C[base + cidx] = v;
        }
    }
}

// ---------------- elementwise kernels ----------------
__device__ __forceinline__ float dsigmoid(float x) { return 1.f / (1.f + expf(-x)); }

__global__ void prep_bias_kernel(const float* __restrict__ bih0, const float* __restrict__ bhh0,
                                 const float* __restrict__ bih1, const float* __restrict__ bhh1)
{
    int i = blockIdx.x * blockDim.x + threadIdx.x;
    if (i < G4H_) {
        g_bias0[i] = bih0[i] + bhh0[i];
        g_bias1[i] = bih1[i] + bhh1[i];
    }
}

__global__ void zero_hc_kernel()
{
    int i = blockIdx.x * blockDim.x + threadIdx.x;
    if (i < B_ * H_) { g_h[i] = 0.f; g_c[i] = 0.f; }
}

// gates layout per row: [i(512) f(512) g(512) o(512)]
__global__ void lstm_cell_kernel(int t, int storeSeq)
{
    int idx = blockIdx.x * blockDim.x + threadIdx.x;
    if (idx >= B_ * H_) return;
    const int b = idx >> 9;          // /512
    const int j = idx & 511;
    const float* gr = g_gates + (size_t)b * G4H_;
    const float ig = dsigmoid(gr[j]);
    const float fg = dsigmoid(gr[H_ + j]);
    const float gg = tanhf(gr[2 * H_ + j]);
    const float og = dsigmoid(gr[3 * H_ + j]);
    const float cn = fg * g_c[idx] + ig * gg;
    const float hn = og * tanhf(cn);
    g_c[idx] = cn;
    g_h[idx] = hn;
    if (storeSeq) g_h1[(size_t)b * (L_ * H_) + (size_t)t * H_ + j] = hn;
}

// top-8 wideband beams per row + build masked mm input. One warp per row.
__global__ void topk_mask_kernel(const float* __restrict__ out_sub, const float* __restrict__ y)
{
    const int warp = (blockIdx.x * blockDim.x + threadIdx.x) >> 5;
    const int lane = threadIdx.x & 31;
    if (warp >= B_) return;
    const float* row = out_sub + (size_t)warp * C_;
    float p = 0.f;
#pragma unroll
    for (int k = 0; k < 8; k++) p += row[lane * 8 + k];

    unsigned selmask = 0;
    float v = p;
#pragma unroll
    for (int it = 0; it < 8; it++) {
        float m = v;
        int mi = lane;
#pragma unroll
        for (int off = 16; off; off >>= 1) {
            const float ov = __shfl_xor_sync(0xffffffffu, m, off);
            const int   oi = __shfl_xor_sync(0xffffffffu, mi, off);
            if (ov > m || (ov == m && oi < mi)) { m = ov; mi = oi; }
        }
        selmask |= 1u << mi;           // all lanes agree on mi
        if (lane == mi) v = -INFINITY;
    }
    const float sel = ((selmask >> lane) & 1u) ? 1.f : 0.f;
    const size_t base = (size_t)warp * FM_ + 2 * lane;
    g_immm[base]     = y[base]     * sel;
    g_immm[base + 1] = y[base + 1] * sel;
}

__global__ void cat_kernel(const float* __restrict__ out_sub, const float* __restrict__ out_mm)
{
    int idx = blockIdx.x * blockDim.x + threadIdx.x;
    if (idx >= B_ * 2 * C_) return;
    const int b = idx >> 9;
    const int j = idx & 511;
    g_cat[idx] = (j < C_) ? out_sub[(size_t)b * C_ + j] : out_mm[(size_t)b * C_ + (j - C_)];
}

// ---------------- host launcher ----------------
static inline void launch_gemm(const float* A, int lda, const float* Bw, int ldb,
                               const float* bias, const float* aux, int ldaux,
                               float* C, int ldc, int M, int N, int K, int epi)
{
    dim3 grid(N / BN, M / BM), block(256);
    sgemm_dual<<<grid, block>>>(A, lda, A, lda, K, Bw, ldb, Bw, ldb,
                                bias, aux, ldaux, C, ldc, M, N, K, epi);
}

extern "C" void kernel_launch(void* const* d_in, const int* in_sizes, int n_in,
                              void* d_out, int out_size)
{
    const float* x    = (const float*)d_in[0];
    const float* y    = (const float*)d_in[1];
    const float* Wih0 = (const float*)d_in[2];
    const float* Whh0 = (const float*)d_in[3];
    const float* bih0 = (const float*)d_in[4];
    const float* bhh0 = (const float*)d_in[5];
    const float* Wih1 = (const float*)d_in[6];
    const float* Whh1 = (const float*)d_in[7];
    const float* bih1 = (const float*)d_in[8];
    const float* bhh1 = (const float*)d_in[9];
    const float* decW = (const float*)d_in[10];
    const float* decb = (const float*)d_in[11];
    const float* mmW1 = (const float*)d_in[12];
    const float* mmb1 = (const float*)d_in[13];
    const float* mmW2 = (const float*)d_in[14];
    const float* mmb2 = (const float*)d_in[15];
    const float* mmW3 = (const float*)d_in[16];
    const float* mmb3 = (const float*)d_in[17];
    const float* attW = (const float*)d_in[18];
    const float* attb = (const float*)d_in[19];
    const float* fuW1 = (const float*)d_in[20];
    const float* fub1 = (const float*)d_in[21];
    const float* fuW2 = (const float*)d_in[22];
    const float* fub2 = (const float*)d_in[23];
    const float* fuW3 = (const float*)d_in[24];
    const float* fub3 = (const float*)d_in[25];

    float* out     = (float*)d_out;
    float* out_sub = out;
    float* out_mm  = out + (size_t)B_ * C_;
    float* out_fu  = out + (size_t)2 * B_ * C_;

    float *gates, *h, *c, *h1, *bs0, *bs1, *immm, *t1, *t2, *cat, *fused;
    cudaGetSymbolAddress((void**)&gates, g_gates);
    cudaGetSymbolAddress((void**)&h,     g_h);
    cudaGetSymbolAddress((void**)&c,     g_c);
    cudaGetSymbolAddress((void**)&h1,    g_h1);
    cudaGetSymbolAddress((void**)&bs0,   g_bias0);
    cudaGetSymbolAddress((void**)&bs1,   g_bias1);
    cudaGetSymbolAddress((void**)&immm,  g_immm);
    cudaGetSymbolAddress((void**)&t1,    g_t1);
    cudaGetSymbolAddress((void**)&t2,    g_t2);
    cudaGetSymbolAddress((void**)&cat,   g_cat);
    cudaGetSymbolAddress((void**)&fused, g_fused);
    (void)c; (void)in_sizes; (void)n_in; (void)out_size;

    const int hcBlocks = (B_ * H_ + 255) / 256;

    prep_bias_kernel<<<(G4H_ + 255) / 256, 256>>>(bih0, bhh0, bih1, bhh1);

    // ---- LSTM layer 0: gates = [x_t | h] @ [Wih0 | Whh0]^T + (bih0+bhh0) ----
    zero_hc_kernel<<<hcBlocks, 256>>>();
    {
        dim3 grid(G4H_ / BN, B_ / BM), block(256);
        for (int t = 0; t < L_; t++) {
            sgemm_dual<<<grid, block>>>(x + (size_t)t * FEAT_, L_ * FEAT_,   // A1 = x[:,t,:]
                                        h, H_, FEAT_,                        // A2 = h, split at KA=128
                                        Wih0, FEAT_, Whh0, H_,
                                        bs0, nullptr, 0,
                                        gates, G4H_, B_, G4H_, FEAT_ + H_, 0);
            lstm_cell_kernel<<<hcBlocks, 256>>>(t, 1);
        }
    }

    // ---- LSTM layer 1: gates = [h1_t | h] @ [Wih1 | Whh1]^T + (bih1+bhh1) ----
    zero_hc_kernel<<<hcBlocks, 256>>>();
    {
        dim3 grid(G4H_ / BN, B_ / BM), block(256);
        for (int t = 0; t < L_; t++) {
            sgemm_dual<<<grid, block>>>(h1 + (size_t)t * H_, L_ * H_,        // A1 = h1[:,t,:]
                                        h, H_, H_,                           // A2 = h, split at KA=512
                                        Wih1, H_, Whh1, H_,
                                        bs1, nullptr, 0,
                                        gates, G4H_, B_, G4H_, 2 * H_, 0);
            lstm_cell_kernel<<<hcBlocks, 256>>>(t, 0);
        }
    }

    // ---- decoder: out_sub = h2_last @ decW^T + decb ----
    launch_gemm(h, H_, decW, H_, decb, nullptr, 0, out_sub, C_, B_, C_, H_, 0);

    // ---- top-8 beam mask -> input_mm ----
    topk_mask_kernel<<<(B_ * 32 + 255) / 256, 256>>>(out_sub, y);

    // ---- mm MLP ----
    launch_gemm(immm, FM_, mmW1, FM_, mmb1, nullptr, 0, t1, H_, B_, H_, FM_, 1);
    launch_gemm(t1, H_, mmW2, H_, mmb2, nullptr, 0, t2, H_, B_, H_, H_, 1);
    launch_gemm(t2, H_, mmW3, H_, mmb3, nullptr, 0, out_mm, C_, B_, C_, H_, 0);

    // ---- gated fusion ----
    cat_kernel<<<(B_ * 2 * C_ + 255) / 256, 256>>>(out_sub, out_mm);
    launch_gemm(cat, 2 * C_, attW, 2 * C_, attb, cat, 2 * C_, fused, 2 * C_, B_, 2 * C_, 2 * C_, 2);
    launch_gemm(fused, 2 * C_, fuW1, 2 * C_, fub1, nullptr, 0, t1, H_, B_, H_, 2 * C_, 1);
    launch_gemm(t1, H_, fuW2, H_, fub2, nullptr, 0, t2, H_, B_, H_, H_, 1);
    launch_gemm(t2, H_, fuW3, H_, fub3, nullptr, 0, out_fu, C_, B_, C_, H_, 0);
}